// round 3
// baseline (speedup 1.0000x reference)
#include <cuda_runtime.h>
#include <math.h>

// Problem dimensions (fixed by the dataset)
#define Bb   8
#define Nn   2048
#define Ee   8192
#define Tt   4096
#define HH   128
#define CD   1024   // B * HID (flattened column dim of the big GEMMs)

// ---------------------------------------------------------------------------
// Scratch (static device globals: allocation-free, graph-capture safe)
// ---------------------------------------------------------------------------
__device__ float g_B1T[(size_t)Ee * Nn];     // 64 MB : B1 transposed [E, N]
__device__ float g_Etopo[(size_t)Ee * CD];   // 32 MB : L1-scaled edge feats [E, B*HID]
__device__ float g_dH[(size_t)Bb * Nn * HH]; //  8 MB : dH before W [B, N, HID]
__device__ float g_L1[Ee];                   // Laplacian diagonal

// ---------------------------------------------------------------------------
// Kernel 1: transpose B1 [N, E] -> g_B1T [E, N]
// ---------------------------------------------------------------------------
__global__ void transpose_b1_kernel(const float* __restrict__ B1) {
    __shared__ float t[32][33];
    const int bx = blockIdx.x * 32;  // e offset
    const int by = blockIdx.y * 32;  // n offset
    const int x = threadIdx.x;       // 0..31
    const int y = threadIdx.y;       // 0..7
#pragma unroll
    for (int i = 0; i < 32; i += 8)
        t[y + i][x] = B1[(size_t)(by + y + i) * Ee + bx + x];
    __syncthreads();
#pragma unroll
    for (int i = 0; i < 32; i += 8)
        g_B1T[(size_t)(bx + y + i) * Nn + by + x] = t[x][y + i];
}

// ---------------------------------------------------------------------------
// Kernel 2: L1_diag[e] = sum_n B1[n,e]^2 + sum_t B2[e,t]^2
// (reads the already-transposed B1T so both reductions are row-contiguous)
// One warp per edge e, float4 vectorized.
// ---------------------------------------------------------------------------
__global__ void l1diag_kernel(const float* __restrict__ B2) {
    const int warp = threadIdx.x >> 5;
    const int lane = threadIdx.x & 31;
    const int e = blockIdx.x * 8 + warp;

    const float* r1 = g_B1T + (size_t)e * Nn;
    float s = 0.f;
    for (int i = lane * 4; i < Nn; i += 128) {
        float4 v = *(const float4*)(r1 + i);
        s += v.x * v.x + v.y * v.y + v.z * v.z + v.w * v.w;
    }
    const float* r2 = B2 + (size_t)e * Tt;
    for (int i = lane * 4; i < Tt; i += 128) {
        float4 v = *(const float4*)(r2 + i);
        s += v.x * v.x + v.y * v.y + v.z * v.z + v.w * v.w;
    }
#pragma unroll
    for (int o = 16; o; o >>= 1) s += __shfl_xor_sync(0xffffffffu, s, o);
    if (lane == 0) g_L1[e] = s;
}

// ---------------------------------------------------------------------------
// Shared 128x128x16 fp32 GEMM body. Both operands are k-major:
//   A[k][m] with row stride lda, B[k][c] with row stride ldb (c-tile = 128).
// C[m][c] with row stride ldc. Optional per-row scale (L1 diag fusion).
// 256 threads, 8x8 register micro-tile, register-staged global prefetch.
// All dims are exact tile multiples -> no predication.
// ---------------------------------------------------------------------------
__device__ __forceinline__ void gemm_body(
    const float* __restrict__ A, int lda,
    const float* __restrict__ Bp, int ldb,
    float* __restrict__ C, int ldc,
    const float* __restrict__ scale, int K)
{
    __shared__ float As[16][128];
    __shared__ float Bs[16][128];

    const int tid  = threadIdx.x;
    const int tx   = tid & 15;       // c micro-tile (8 cols)
    const int ty   = tid >> 4;       // m micro-tile (8 rows)
    const int m0   = blockIdx.x * 128;
    const int lrow = tid >> 5;       // 0..7 (k rows; each thread also loads lrow+8)
    const int lcol = (tid & 31) * 4; // 0..124

    const float* Ag = A  + (size_t)lrow * lda + m0 + lcol;
    const float* Bg = Bp + (size_t)lrow * ldb + lcol;

    float acc[8][8];
#pragma unroll
    for (int i = 0; i < 8; i++)
#pragma unroll
        for (int j = 0; j < 8; j++) acc[i][j] = 0.f;

    // Prefetch first tile into registers
    float4 a0 = *(const float4*)(Ag);
    float4 a1 = *(const float4*)(Ag + 8 * (size_t)lda);
    float4 b0 = *(const float4*)(Bg);
    float4 b1 = *(const float4*)(Bg + 8 * (size_t)ldb);

    for (int k0 = 0; k0 < K; k0 += 16) {
        __syncthreads();
        *(float4*)&As[lrow][lcol]     = a0;
        *(float4*)&As[lrow + 8][lcol] = a1;
        *(float4*)&Bs[lrow][lcol]     = b0;
        *(float4*)&Bs[lrow + 8][lcol] = b1;
        __syncthreads();

        if (k0 + 16 < K) {  // prefetch next tile while computing this one
            Ag += 16 * (size_t)lda;
            Bg += 16 * (size_t)ldb;
            a0 = *(const float4*)(Ag);
            a1 = *(const float4*)(Ag + 8 * (size_t)lda);
            b0 = *(const float4*)(Bg);
            b1 = *(const float4*)(Bg + 8 * (size_t)ldb);
        }

#pragma unroll
        for (int kk = 0; kk < 16; kk++) {
            float a[8], b[8];
            *(float4*)(a)     = *(const float4*)&As[kk][ty * 8];
            *(float4*)(a + 4) = *(const float4*)&As[kk][ty * 8 + 4];
            *(float4*)(b)     = *(const float4*)&Bs[kk][tx * 8];
            *(float4*)(b + 4) = *(const float4*)&Bs[kk][tx * 8 + 4];
#pragma unroll
            for (int i = 0; i < 8; i++)
#pragma unroll
                for (int j = 0; j < 8; j++)
                    acc[i][j] = fmaf(a[i], b[j], acc[i][j]);
        }
    }

#pragma unroll
    for (int i = 0; i < 8; i++) {
        const int m = m0 + ty * 8 + i;
        const float s = scale ? scale[m] : 1.0f;
        float* Cr = C + (size_t)m * ldc + tx * 8;
        float4 v0, v1;
        v0.x = acc[i][0] * s; v0.y = acc[i][1] * s;
        v0.z = acc[i][2] * s; v0.w = acc[i][3] * s;
        v1.x = acc[i][4] * s; v1.y = acc[i][5] * s;
        v1.z = acc[i][6] * s; v1.w = acc[i][7] * s;
        *(float4*)(Cr)     = v0;
        *(float4*)(Cr + 4) = v1;
    }
}

// GEMM1: Etopo[e, b*128+h] = L1[e] * sum_n B1[n,e] * H[b,n,h]
// blockIdx.y = batch b (c-block). A = B1 (k-major: k=n rows, e contiguous).
__global__ __launch_bounds__(256, 2)
void gemm1_kernel(const float* __restrict__ B1, const float* __restrict__ H) {
    gemm_body(B1, Ee,
              H + (size_t)blockIdx.y * (Nn * HH), HH,
              g_Etopo + (size_t)blockIdx.y * HH, CD,
              g_L1, Nn);
}

// GEMM2: dH[b,n,h] = sum_e B1T[e,n] * Etopo[e, b*128+h]
__global__ __launch_bounds__(256, 2)
void gemm2_kernel() {
    gemm_body(g_B1T, Nn,
              g_Etopo + (size_t)blockIdx.y * HH, CD,
              g_dH + (size_t)blockIdx.y * (Nn * HH), HH,
              nullptr, Ee);
}

// ---------------------------------------------------------------------------
// Kernel 5: out[b,n,o] = H[b,n,o] + alpha * relu( sum_h dH[b,n,h] * W[o,h] )
// 16384x128x128 GEMM, 128-row tiles, both operands transposed into SMEM.
// ---------------------------------------------------------------------------
__global__ __launch_bounds__(256)
void final_kernel(const float* __restrict__ H, const float* __restrict__ W,
                  const float* __restrict__ alpha_raw, float* __restrict__ out)
{
    __shared__ float As[32][132];  // As[h'][m]  (dH tile, transposed)
    __shared__ float Ws[32][132];  // Ws[h'][o]  (W tile, transposed)

    const int tid = threadIdx.x;
    const int tx  = tid & 15;
    const int ty  = tid >> 4;
    const int m0  = blockIdx.x * 128;   // row in flattened [B*N]
    const int r   = tid >> 3;           // 0..31
    const int c4  = (tid & 7) * 4;      // 0,4,...,28

    float acc[8][8];
#pragma unroll
    for (int i = 0; i < 8; i++)
#pragma unroll
        for (int j = 0; j < 8; j++) acc[i][j] = 0.f;

    for (int h0 = 0; h0 < HH; h0 += 32) {
        __syncthreads();
#pragma unroll
        for (int p = 0; p < 4; p++) {
            const int row = r + p * 32;  // 0..127
            float4 av = *(const float4*)(g_dH + (size_t)(m0 + row) * HH + h0 + c4);
            As[c4 + 0][row] = av.x; As[c4 + 1][row] = av.y;
            As[c4 + 2][row] = av.z; As[c4 + 3][row] = av.w;
            float4 wv = *(const float4*)(W + (size_t)row * HH + h0 + c4);
            Ws[c4 + 0][row] = wv.x; Ws[c4 + 1][row] = wv.y;
            Ws[c4 + 2][row] = wv.z; Ws[c4 + 3][row] = wv.w;
        }
        __syncthreads();
#pragma unroll
        for (int kk = 0; kk < 32; kk++) {
            float a[8], w[8];
            *(float4*)(a)     = *(const float4*)&As[kk][ty * 8];
            *(float4*)(a + 4) = *(const float4*)&As[kk][ty * 8 + 4];
            *(float4*)(w)     = *(const float4*)&Ws[kk][tx * 8];
            *(float4*)(w + 4) = *(const float4*)&Ws[kk][tx * 8 + 4];
#pragma unroll
            for (int i = 0; i < 8; i++)
#pragma unroll
                for (int j = 0; j < 8; j++)
                    acc[i][j] = fmaf(a[i], w[j], acc[i][j]);
        }
    }

    const float alpha = 0.05f / (1.0f + expf(-alpha_raw[0]));

#pragma unroll
    for (int i = 0; i < 8; i++) {
        const size_t m = (size_t)m0 + ty * 8 + i;
        const float* Hr = H + m * HH + tx * 8;
        float* Or = out + m * HH + tx * 8;
#pragma unroll
        for (int j = 0; j < 8; j++)
            Or[j] = Hr[j] + alpha * fmaxf(acc[i][j], 0.f);
    }
}

// ---------------------------------------------------------------------------
// Launch: all on the capture stream; stream order carries dependencies.
// ---------------------------------------------------------------------------
extern "C" void kernel_launch(void* const* d_in, const int* in_sizes, int n_in,
                              void* d_out, int out_size) {
    const float* H   = (const float*)d_in[0];
    const float* B1  = (const float*)d_in[1];
    const float* B2  = (const float*)d_in[2];
    const float* W   = (const float*)d_in[3];
    const float* ar  = (const float*)d_in[4];
    float* out = (float*)d_out;

    transpose_b1_kernel<<<dim3(Ee / 32, Nn / 32), dim3(32, 8)>>>(B1);
    l1diag_kernel<<<Ee / 8, 256>>>(B2);
    gemm1_kernel<<<dim3(Ee / 128, Bb), 256>>>(B1, H);
    gemm2_kernel<<<dim3(Nn / 128, Bb), 256>>>();
    final_kernel<<<(Bb * Nn) / 128, 256>>>(H, W, ar, out);
}

// round 10
// speedup vs baseline: 2.1160x; 2.1160x over previous
#include <cuda_runtime.h>
#include <cuda_bf16.h>
#include <cstdint>
#include <math.h>

// Problem dims
#define Bb   8
#define Nn   2048
#define Ee   8192
#define Tt   4096
#define HH   128
#define CD   1024   // B*HH

// ---------------------------------------------------------------------------
// Scratch (static device globals). NEVER pass these as kernel arguments from
// host code: the host sees only the shadow symbol, and GB300's ATS makes the
// resulting host-address writes *succeed silently* (R8/R9 bug). All bindings
// happen inside device code.
// ---------------------------------------------------------------------------
__device__ __nv_bfloat16 g_B1T_hi[(size_t)Ee * Nn];      // B1^T  [E,N]
__device__ __nv_bfloat16 g_B1T_lo[(size_t)Ee * Nn];
__device__ __nv_bfloat16 g_B1_hi [(size_t)Nn * Ee];      // B1    [N,E]
__device__ __nv_bfloat16 g_B1_lo [(size_t)Nn * Ee];
__device__ __nv_bfloat16 g_HT_hi [(size_t)Bb * HH * Nn]; // H^T [b][h][n]
__device__ __nv_bfloat16 g_HT_lo [(size_t)Bb * HH * Nn];
__device__ float         g_Et32  [(size_t)Ee * CD];      // Etopo [e][b*128+h] fp32
__device__ __nv_bfloat16 g_EtT_hi[(size_t)CD * Ee];      // Etopo^T [b*128+h][e]
__device__ __nv_bfloat16 g_EtT_lo[(size_t)CD * Ee];
__device__ float g_dH[(size_t)Bb * Nn * HH];
__device__ float g_L1[Ee];
__device__ float g_L1part[64][Ee];

// ---------------------------------------------------------------------------
// Base-ISA helpers (sm_80 features only — plain compute_103 safe)
// ---------------------------------------------------------------------------
__device__ __forceinline__ uint32_t smem_to_u32(const void* p) {
    uint32_t a;
    asm("{ .reg .u64 t; cvta.to.shared.u64 t, %1; cvt.u32.u64 %0, t; }"
        : "=r"(a) : "l"(p));
    return a;
}
#define CP_COMMIT() asm volatile("cp.async.commit_group;" ::: "memory")
#define CP_WAIT(n)  asm volatile("cp.async.wait_group %0;" :: "n"(n) : "memory")

__device__ __forceinline__ void cp_async16(uint32_t dst, const void* src) {
    asm volatile("cp.async.cg.shared.global [%0], [%1], 16;" :: "r"(dst), "l"(src));
}
__device__ __forceinline__ void mma_bf16(float d[4], const uint32_t a[4],
                                         const uint32_t b[2]) {
    asm volatile(
        "mma.sync.aligned.m16n8k16.row.col.f32.bf16.bf16.f32 "
        "{%0,%1,%2,%3}, {%4,%5,%6,%7}, {%8,%9}, {%0,%1,%2,%3};"
        : "+f"(d[0]), "+f"(d[1]), "+f"(d[2]), "+f"(d[3])
        : "r"(a[0]), "r"(a[1]), "r"(a[2]), "r"(a[3]), "r"(b[0]), "r"(b[1]));
}
__device__ __forceinline__ void bf16_split(float a, __nv_bfloat16& h, __nv_bfloat16& l) {
    h = __float2bfloat16(a);
    l = __float2bfloat16(a - __bfloat162float(h));
}
__device__ __forceinline__ uint32_t lds_u32(const char* p) {
    return *(const uint32_t*)p;   // p derived from extern __shared__ -> LDS
}

// ---------------------------------------------------------------------------
// Transpose + bf16 hi/lo split body (32x32 tiles). Pointers are bound by the
// __global__ wrappers below, in DEVICE code.
// ---------------------------------------------------------------------------
__device__ __forceinline__ void tsplit_body(
    const float* __restrict__ in, int ld_in,
    __nv_bfloat16* __restrict__ hi, __nv_bfloat16* __restrict__ lo,
    int ld_out, int do_l1) {
    __shared__ float t[32][33];
    __shared__ float ps[8][32];
    const int r0 = blockIdx.y * 32, c0 = blockIdx.x * 32;
    const int x = threadIdx.x, y = threadIdx.y;
    float s = 0.f;
#pragma unroll
    for (int i = 0; i < 32; i += 8) {
        float v = in[(size_t)(r0 + y + i) * ld_in + c0 + x];
        t[y + i][x] = v;
        s += v * v;
    }
    if (do_l1) ps[y][x] = s;
    __syncthreads();
    if (do_l1 && y == 0) {
        float tot = 0.f;
#pragma unroll
        for (int k = 0; k < 8; k++) tot += ps[k][x];
        g_L1part[blockIdx.y][c0 + x] = tot;
    }
#pragma unroll
    for (int i = 0; i < 32; i += 8) {
        float v = t[x][y + i];
        __nv_bfloat16 h, l;
        bf16_split(v, h, l);
        size_t o = (size_t)(c0 + y + i) * ld_out + r0 + x;
        hi[o] = h; lo[o] = l;
    }
}

// B1 [N,E] -> g_B1T hi/lo [E,N], plus L1 partial sums per 32-row n-block.
__global__ void tsplit_b1_kernel(const float* __restrict__ B1) {
    tsplit_body(B1, Ee, g_B1T_hi, g_B1T_lo, Nn, 1);
}
// H [b][n][h] -> g_HT hi/lo [b][h][n]
__global__ void tsplit_h_kernel(const float* __restrict__ H) {
    const size_t ib = (size_t)blockIdx.z * (Nn * HH);
    const size_t ob = (size_t)blockIdx.z * (HH * Nn);
    tsplit_body(H + ib, HH, g_HT_hi + ob, g_HT_lo + ob, Nn, 0);
}
// Et32 [E][CD] -> g_EtT hi/lo [CD][E]
__global__ void tsplit_et_kernel() {
    tsplit_body(g_Et32, CD, g_EtT_hi, g_EtT_lo, Ee, 0);
}

// B1 -> bf16 hi/lo, same [N,E] layout (GEMM2 A operand)
__global__ void split_b1_kernel(const float* __restrict__ in) {
    size_t i = ((size_t)blockIdx.x * 256 + threadIdx.x) * 4;
    float4 v = *(const float4*)(in + i);
    __nv_bfloat16 h, l;
    bf16_split(v.x, h, l); g_B1_hi[i]     = h; g_B1_lo[i]     = l;
    bf16_split(v.y, h, l); g_B1_hi[i + 1] = h; g_B1_lo[i + 1] = l;
    bf16_split(v.z, h, l); g_B1_hi[i + 2] = h; g_B1_lo[i + 2] = l;
    bf16_split(v.w, h, l); g_B1_hi[i + 3] = h; g_B1_lo[i + 3] = l;
}

__global__ void l1_finalize_kernel(const float* __restrict__ B2) {
    const int warp = threadIdx.x >> 5, lane = threadIdx.x & 31;
    const int e = blockIdx.x * 8 + warp;
    float s = 0.f;
#pragma unroll
    for (int p = lane; p < 64; p += 32) s += g_L1part[p][e];
    const float* r2 = B2 + (size_t)e * Tt;
    for (int i = lane * 4; i < Tt; i += 128) {
        float4 v = *(const float4*)(r2 + i);
        s += v.x * v.x + v.y * v.y + v.z * v.z + v.w * v.w;
    }
#pragma unroll
    for (int o = 16; o; o >>= 1) s += __shfl_xor_sync(0xffffffffu, s, o);
    if (lane == 0) g_L1[e] = s;
}

// ---------------------------------------------------------------------------
// mma.sync GEMM core, explicit-coordinate fragments (no ldmatrix, no swizzle).
// C[128,128] += A[128,K]*B[128,K]^T, hi/lo bf16, 3-MMA fp32 emulation.
// SMEM rows padded to 144B -> conflict-free fragment LDS.
// 2-stage cp.async double buffer; 8 warps = 2(m) x 4(n); warp tile 64x32.
// ---------------------------------------------------------------------------
#define ROWB     144
#define TILE_B   (128 * ROWB)        // 18432
#define STAGE_B  (4 * TILE_B)        // 73728
#define SMEM_DYN (2 * STAGE_B)       // 147456

__device__ __forceinline__ void load_tile_ca(uint32_t dst,
                                             const __nv_bfloat16* __restrict__ src,
                                             int ld, int tid) {
#pragma unroll
    for (int i = 0; i < 4; i++) {
        const int lin = tid + i * 256;
        const int row = lin >> 3, c = lin & 7;
        cp_async16(dst + (uint32_t)(row * ROWB + c * 16),
                   src + (size_t)row * ld + c * 8);
    }
}

__device__ __forceinline__ void load_stage(uint32_t sb,
    const __nv_bfloat16* Ahi, const __nv_bfloat16* Alo, int lda,
    const __nv_bfloat16* Bhi, const __nv_bfloat16* Blo, int ldb,
    int k0, int tid) {
    load_tile_ca(sb,              Ahi + k0, lda, tid);
    load_tile_ca(sb + TILE_B,     Alo + k0, lda, tid);
    load_tile_ca(sb + 2 * TILE_B, Bhi + k0, ldb, tid);
    load_tile_ca(sb + 3 * TILE_B, Blo + k0, ldb, tid);
}

__device__ __forceinline__ void gemm_mainloop(char* smem,
    const __nv_bfloat16* __restrict__ Ahi, const __nv_bfloat16* __restrict__ Alo, int lda,
    const __nv_bfloat16* __restrict__ Bhi, const __nv_bfloat16* __restrict__ Blo, int ldb,
    int nT, float (&acc)[4][4][4]) {
    const int tid = threadIdx.x;
    const int wid = tid >> 5, lane = tid & 31;
    const int wm = wid & 1, wn = wid >> 1;
    const int g = lane >> 2, tig = lane & 3;
    const uint32_t su = smem_to_u32(smem);

    // Fragment base offsets (PTX m16n8k16 fragment tables, bytes):
    //   A a0=(g, 2tig..+1), a1=(g+8, k0), a2=(g, k+8), a3=(g+8, k+8)
    //   B b0=(k=2tig..+1, n=g), b1=(k+8, n=g); stored [n][k] k-contiguous.
    const int aoff = (wm * 64 + g) * ROWB + tig * 4;
    const int boff = (wn * 32 + g) * ROWB + tig * 4;

    load_stage(su, Ahi, Alo, lda, Bhi, Blo, ldb, 0, tid);
    CP_COMMIT();

    for (int it = 0; it < nT; ++it) {
        const uint32_t sb = (uint32_t)(it & 1) * STAGE_B;
        if (it + 1 < nT) {
            load_stage(su + (uint32_t)((it + 1) & 1) * STAGE_B,
                       Ahi, Alo, lda, Bhi, Blo, ldb, (it + 1) * 64, tid);
            CP_COMMIT();
            CP_WAIT(1);
        } else {
            CP_WAIT(0);
        }
        __syncthreads();

        const char* As = smem + sb;
        const char* Bs = smem + sb + 2 * TILE_B;
#pragma unroll
        for (int kk = 0; kk < 4; kk++) {
            uint32_t ah[4][4], al[4][4], bh[4][2], bl[4][2];
#pragma unroll
            for (int mi = 0; mi < 4; mi++) {
                const char* p = As + aoff + mi * 16 * ROWB + kk * 32;
                ah[mi][0] = lds_u32(p);
                ah[mi][1] = lds_u32(p + 8 * ROWB);
                ah[mi][2] = lds_u32(p + 16);
                ah[mi][3] = lds_u32(p + 8 * ROWB + 16);
                al[mi][0] = lds_u32(p + TILE_B);
                al[mi][1] = lds_u32(p + TILE_B + 8 * ROWB);
                al[mi][2] = lds_u32(p + TILE_B + 16);
                al[mi][3] = lds_u32(p + TILE_B + 8 * ROWB + 16);
            }
#pragma unroll
            for (int ni = 0; ni < 4; ni++) {
                const char* p = Bs + boff + ni * 8 * ROWB + kk * 32;
                bh[ni][0] = lds_u32(p);
                bh[ni][1] = lds_u32(p + 16);
                bl[ni][0] = lds_u32(p + TILE_B);
                bl[ni][1] = lds_u32(p + TILE_B + 16);
            }
#pragma unroll
            for (int mi = 0; mi < 4; mi++)
#pragma unroll
                for (int ni = 0; ni < 4; ni++) {
                    mma_bf16(acc[mi][ni], ah[mi], bh[ni]);
                    mma_bf16(acc[mi][ni], ah[mi], bl[ni]);
                    mma_bf16(acc[mi][ni], al[mi], bh[ni]);
                }
        }
        __syncthreads();
    }
}

// GEMM1: Et32[e][cb*128+h] = L1[e] * sum_n B1T[e,n]*HT[cb][h][n]
__global__ __launch_bounds__(256, 1) void gemm1_kernel() {
    extern __shared__ char smem[];
    float acc[4][4][4];
#pragma unroll
    for (int i = 0; i < 4; i++)
#pragma unroll
        for (int j = 0; j < 4; j++)
#pragma unroll
            for (int k = 0; k < 4; k++) acc[i][j][k] = 0.f;

    const int m0 = blockIdx.x * 128;   // e block
    const int cb = blockIdx.y;         // batch
    gemm_mainloop(smem,
                  g_B1T_hi + (size_t)m0 * Nn, g_B1T_lo + (size_t)m0 * Nn, Nn,
                  g_HT_hi + (size_t)cb * HH * Nn, g_HT_lo + (size_t)cb * HH * Nn, Nn,
                  Nn / 64, acc);

    const int tid = threadIdx.x, lane = tid & 31, wid = tid >> 5;
    const int wm = wid & 1, wn = wid >> 1;
    const int g = lane >> 2, tig = lane & 3;
#pragma unroll
    for (int mi = 0; mi < 4; mi++) {
        const int e = m0 + wm * 64 + mi * 16 + g;
        const float s0 = g_L1[e], s1 = g_L1[e + 8];
        float* r0 = g_Et32 + (size_t)e * CD + cb * 128;
#pragma unroll
        for (int ni = 0; ni < 4; ni++) {
            const int c = wn * 32 + ni * 8 + 2 * tig;
            *(float2*)(r0 + c) = make_float2(acc[mi][ni][0] * s0, acc[mi][ni][1] * s0);
            *(float2*)(r0 + 8 * CD + c) =
                make_float2(acc[mi][ni][2] * s1, acc[mi][ni][3] * s1);
        }
    }
}

// GEMM2: dH[cb][n][h] = sum_e B1[n,e]*EtT[cb*128+h][e]
__global__ __launch_bounds__(256, 1) void gemm2_kernel() {
    extern __shared__ char smem[];
    float acc[4][4][4];
#pragma unroll
    for (int i = 0; i < 4; i++)
#pragma unroll
        for (int j = 0; j < 4; j++)
#pragma unroll
            for (int k = 0; k < 4; k++) acc[i][j][k] = 0.f;

    const int m0 = blockIdx.x * 128;   // n block
    const int cb = blockIdx.y;         // batch
    gemm_mainloop(smem,
                  g_B1_hi + (size_t)m0 * Ee, g_B1_lo + (size_t)m0 * Ee, Ee,
                  g_EtT_hi + (size_t)cb * 128 * Ee, g_EtT_lo + (size_t)cb * 128 * Ee, Ee,
                  Ee / 64, acc);

    const int tid = threadIdx.x, lane = tid & 31, wid = tid >> 5;
    const int wm = wid & 1, wn = wid >> 1;
    const int g = lane >> 2, tig = lane & 3;
#pragma unroll
    for (int mi = 0; mi < 4; mi++) {
        const int gn = m0 + wm * 64 + mi * 16 + g;
        float* r0 = g_dH + ((size_t)cb * Nn + gn) * HH;
        float* r1 = r0 + 8 * HH;
#pragma unroll
        for (int ni = 0; ni < 4; ni++) {
            const int h = wn * 32 + ni * 8 + 2 * tig;
            *(float2*)(r0 + h) = make_float2(acc[mi][ni][0], acc[mi][ni][1]);
            *(float2*)(r1 + h) = make_float2(acc[mi][ni][2], acc[mi][ni][3]);
        }
    }
}

// ---------------------------------------------------------------------------
// Final: out = H + alpha * relu( dH @ W^T )   (SIMT; validated in R3)
// ---------------------------------------------------------------------------
__global__ __launch_bounds__(256) void final_kernel(
    const float* __restrict__ H, const float* __restrict__ W,
    const float* __restrict__ alpha_raw, float* __restrict__ out) {
    __shared__ float As[32][132];
    __shared__ float Ws[32][132];
    const int tid = threadIdx.x;
    const int tx = tid & 15, ty = tid >> 4;
    const int m0 = blockIdx.x * 128;
    const int r = tid >> 3, c4 = (tid & 7) * 4;

    float acc[8][8];
#pragma unroll
    for (int i = 0; i < 8; i++)
#pragma unroll
        for (int j = 0; j < 8; j++) acc[i][j] = 0.f;

    for (int h0 = 0; h0 < HH; h0 += 32) {
        __syncthreads();
#pragma unroll
        for (int p = 0; p < 4; p++) {
            const int row = r + p * 32;
            float4 av = *(const float4*)(g_dH + (size_t)(m0 + row) * HH + h0 + c4);
            As[c4 + 0][row] = av.x; As[c4 + 1][row] = av.y;
            As[c4 + 2][row] = av.z; As[c4 + 3][row] = av.w;
            float4 wv = *(const float4*)(W + (size_t)row * HH + h0 + c4);
            Ws[c4 + 0][row] = wv.x; Ws[c4 + 1][row] = wv.y;
            Ws[c4 + 2][row] = wv.z; Ws[c4 + 3][row] = wv.w;
        }
        __syncthreads();
#pragma unroll
        for (int kk = 0; kk < 32; kk++) {
            float a[8], w[8];
            *(float4*)(a)     = *(const float4*)&As[kk][ty * 8];
            *(float4*)(a + 4) = *(const float4*)&As[kk][ty * 8 + 4];
            *(float4*)(w)     = *(const float4*)&Ws[kk][tx * 8];
            *(float4*)(w + 4) = *(const float4*)&Ws[kk][tx * 8 + 4];
#pragma unroll
            for (int i = 0; i < 8; i++)
#pragma unroll
                for (int j = 0; j < 8; j++)
                    acc[i][j] = fmaf(a[i], w[j], acc[i][j]);
        }
    }

    const float alpha = 0.05f / (1.0f + expf(-alpha_raw[0]));
#pragma unroll
    for (int i = 0; i < 8; i++) {
        const size_t m = (size_t)m0 + ty * 8 + i;
        const float* Hr = H + m * HH + tx * 8;
        float* Or = out + m * HH + tx * 8;
#pragma unroll
        for (int j = 0; j < 8; j++)
            Or[j] = Hr[j] + alpha * fmaxf(acc[i][j], 0.f);
    }
}

// ---------------------------------------------------------------------------
extern "C" void kernel_launch(void* const* d_in, const int* in_sizes, int n_in,
                              void* d_out, int out_size) {
    const float* H  = (const float*)d_in[0];
    const float* B1 = (const float*)d_in[1];
    const float* B2 = (const float*)d_in[2];
    const float* W  = (const float*)d_in[3];
    const float* ar = (const float*)d_in[4];
    float* out = (float*)d_out;

    cudaFuncSetAttribute(gemm1_kernel, cudaFuncAttributeMaxDynamicSharedMemorySize, SMEM_DYN);
    cudaFuncSetAttribute(gemm2_kernel, cudaFuncAttributeMaxDynamicSharedMemorySize, SMEM_DYN);

    // B1 [N,E] -> B1T hi/lo [E,N]  (+ L1 partials per 32-row n-block)
    tsplit_b1_kernel<<<dim3(Ee / 32, Nn / 32, 1), dim3(32, 8)>>>(B1);
    // B1 -> bf16 hi/lo (same [N,E] layout; GEMM2 A operand)
    split_b1_kernel<<<((size_t)Nn * Ee) / (256 * 4), 256>>>(B1);
    // H [b][n][h] -> HT hi/lo [b][h][n]
    tsplit_h_kernel<<<dim3(HH / 32, Nn / 32, Bb), dim3(32, 8)>>>(H);
    // L1[e] = sum partials + rowsum(B2^2)
    l1_finalize_kernel<<<Ee / 8, 256>>>(B2);

    // GEMM1 -> Et32 fp32 [E][CD]
    gemm1_kernel<<<dim3(Ee / 128, Bb), 256, SMEM_DYN>>>();
    // Et32 [E][CD] -> EtT hi/lo [CD][E]
    tsplit_et_kernel<<<dim3(CD / 32, Ee / 32, 1), dim3(32, 8)>>>();
    // GEMM2 -> dH
    gemm2_kernel<<<dim3(Nn / 128, Bb), 256, SMEM_DYN>>>();
    final_kernel<<<(Bb * Nn) / 128, 256>>>(H, W, ar, out);
}

// round 11
// speedup vs baseline: 2.1692x; 1.0251x over previous
#include <cuda_runtime.h>
#include <cuda_bf16.h>
#include <cstdint>
#include <math.h>

// Problem dims
#define Bb   8
#define Nn   2048
#define Ee   8192
#define Tt   4096
#define HH   128
#define CD   1024   // B*HH

// ---------------------------------------------------------------------------
// Scratch (static device globals). NEVER pass these as kernel arguments from
// host code (host shadow symbol + GB300 ATS silently writes host memory —
// the R8/R9 bug). All bindings happen inside device code.
// ---------------------------------------------------------------------------
__device__ __nv_bfloat16 g_B1T_hi[(size_t)Ee * Nn];      // B1^T  [E,N]
__device__ __nv_bfloat16 g_B1T_lo[(size_t)Ee * Nn];
__device__ __nv_bfloat16 g_B1_hi [(size_t)Nn * Ee];      // B1    [N,E]
__device__ __nv_bfloat16 g_B1_lo [(size_t)Nn * Ee];
__device__ __nv_bfloat16 g_HT_hi [(size_t)Bb * HH * Nn]; // H^T [b][h][n]
__device__ __nv_bfloat16 g_HT_lo [(size_t)Bb * HH * Nn];
__device__ float         g_Et32  [(size_t)Ee * CD];      // Etopo [e][b*128+h] fp32
__device__ __nv_bfloat16 g_EtT_hi[(size_t)CD * Ee];      // Etopo^T [b*128+h][e]
__device__ __nv_bfloat16 g_EtT_lo[(size_t)CD * Ee];
__device__ float g_dH[(size_t)2 * Bb * Nn * HH];         // 2 K-split partials
__device__ float g_L1[Ee];
__device__ float g_L1part[64][Ee];

// ---------------------------------------------------------------------------
// Base-ISA helpers (sm_80 features only — plain compute_103 safe)
// ---------------------------------------------------------------------------
__device__ __forceinline__ uint32_t smem_to_u32(const void* p) {
    uint32_t a;
    asm("{ .reg .u64 t; cvta.to.shared.u64 t, %1; cvt.u32.u64 %0, t; }"
        : "=r"(a) : "l"(p));
    return a;
}
#define CP_COMMIT() asm volatile("cp.async.commit_group;" ::: "memory")
#define CP_WAIT(n)  asm volatile("cp.async.wait_group %0;" :: "n"(n) : "memory")

__device__ __forceinline__ void cp_async16(uint32_t dst, const void* src) {
    asm volatile("cp.async.cg.shared.global [%0], [%1], 16;" :: "r"(dst), "l"(src));
}
__device__ __forceinline__ void ldsm_x4(uint32_t& r0, uint32_t& r1,
                                        uint32_t& r2, uint32_t& r3, uint32_t a) {
    asm volatile("ldmatrix.sync.aligned.m8n8.x4.shared.b16 {%0,%1,%2,%3}, [%4];"
                 : "=r"(r0), "=r"(r1), "=r"(r2), "=r"(r3) : "r"(a));
}
__device__ __forceinline__ void mma_bf16(float d[4], const uint32_t a[4],
                                         const uint32_t b[2]) {
    asm volatile(
        "mma.sync.aligned.m16n8k16.row.col.f32.bf16.bf16.f32 "
        "{%0,%1,%2,%3}, {%4,%5,%6,%7}, {%8,%9}, {%0,%1,%2,%3};"
        : "+f"(d[0]), "+f"(d[1]), "+f"(d[2]), "+f"(d[3])
        : "r"(a[0]), "r"(a[1]), "r"(a[2]), "r"(a[3]), "r"(b[0]), "r"(b[1]));
}
__device__ __forceinline__ void bf16_split(float a, __nv_bfloat16& h, __nv_bfloat16& l) {
    h = __float2bfloat16(a);
    l = __float2bfloat16(a - __bfloat162float(h));
}

// ---------------------------------------------------------------------------
// Prep kernels. tsplit = 32x32 transpose + bf16 hi/lo split.
// ---------------------------------------------------------------------------
__device__ __forceinline__ void tsplit_body(
    const float* __restrict__ in, int ld_in,
    __nv_bfloat16* __restrict__ hi, __nv_bfloat16* __restrict__ lo,
    int ld_out) {
    __shared__ float t[32][33];
    const int r0 = blockIdx.y * 32, c0 = blockIdx.x * 32;
    const int x = threadIdx.x, y = threadIdx.y;
#pragma unroll
    for (int i = 0; i < 32; i += 8)
        t[y + i][x] = in[(size_t)(r0 + y + i) * ld_in + c0 + x];
    __syncthreads();
#pragma unroll
    for (int i = 0; i < 32; i += 8) {
        float v = t[x][y + i];
        __nv_bfloat16 h, l;
        bf16_split(v, h, l);
        size_t o = (size_t)(c0 + y + i) * ld_out + r0 + x;
        hi[o] = h; lo[o] = l;
    }
}

// B1 [N,E]: emits B1T hi/lo [E,N] (transposed), B1 hi/lo [N,E] (straight),
// and per-32-row-block L1 partial sums. One read of B1.
__global__ void tsplit_b1_kernel(const float* __restrict__ B1) {
    __shared__ float t[32][33];
    __shared__ float ps[8][32];
    const int r0 = blockIdx.y * 32, c0 = blockIdx.x * 32;
    const int x = threadIdx.x, y = threadIdx.y;
    float s = 0.f;
#pragma unroll
    for (int i = 0; i < 32; i += 8) {
        float v = B1[(size_t)(r0 + y + i) * Ee + c0 + x];
        t[y + i][x] = v;
        s += v * v;
        __nv_bfloat16 h, l;
        bf16_split(v, h, l);
        const size_t o = (size_t)(r0 + y + i) * Ee + c0 + x;
        g_B1_hi[o] = h; g_B1_lo[o] = l;
    }
    ps[y][x] = s;
    __syncthreads();
    if (y == 0) {
        float tot = 0.f;
#pragma unroll
        for (int k = 0; k < 8; k++) tot += ps[k][x];
        g_L1part[blockIdx.y][c0 + x] = tot;
    }
#pragma unroll
    for (int i = 0; i < 32; i += 8) {
        float v = t[x][y + i];
        __nv_bfloat16 h, l;
        bf16_split(v, h, l);
        size_t o = (size_t)(c0 + y + i) * Nn + r0 + x;
        g_B1T_hi[o] = h; g_B1T_lo[o] = l;
    }
}

// H [b][n][h] -> g_HT hi/lo [b][h][n]
__global__ void tsplit_h_kernel(const float* __restrict__ H) {
    const size_t ib = (size_t)blockIdx.z * (Nn * HH);
    const size_t ob = (size_t)blockIdx.z * (HH * Nn);
    tsplit_body(H + ib, HH, g_HT_hi + ob, g_HT_lo + ob, Nn);
}
// Et32 [E][CD] -> g_EtT hi/lo [CD][E]
__global__ void tsplit_et_kernel() {
    tsplit_body(g_Et32, CD, g_EtT_hi, g_EtT_lo, Ee);
}

__global__ void l1_finalize_kernel(const float* __restrict__ B2) {
    const int warp = threadIdx.x >> 5, lane = threadIdx.x & 31;
    const int e = blockIdx.x * 8 + warp;
    float s = 0.f;
#pragma unroll
    for (int p = lane; p < 64; p += 32) s += g_L1part[p][e];
    const float* r2 = B2 + (size_t)e * Tt;
    for (int i = lane * 4; i < Tt; i += 128) {
        float4 v = *(const float4*)(r2 + i);
        s += v.x * v.x + v.y * v.y + v.z * v.z + v.w * v.w;
    }
#pragma unroll
    for (int o = 16; o; o >>= 1) s += __shfl_xor_sync(0xffffffffu, s, o);
    if (lane == 0) g_L1[e] = s;
}

// ---------------------------------------------------------------------------
// mma.sync GEMM core with ldmatrix fragments.
// C[128,128] += A[128,K]*B[128,K]^T, hi/lo bf16, 3-MMA fp32 emulation.
// K-tile 32, rows of 64B, XOR swizzle chunk' = chunk ^ ((row>>1)&3)
// (conflict-free for both cp.async stores and 8-row ldmatrix groups).
// 3-stage cp.async pipeline, 96KB smem -> 2 CTAs/SM. 8 warps = 2(m) x 4(n).
// ---------------------------------------------------------------------------
#define KT        32
#define ROWBYTES  64
#define TILE_BS   8192                 // 128 rows * 64B
#define STAGE_BS  (4 * TILE_BS)        // Ahi Alo Bhi Blo = 32KB
#define NSTAGE    3
#define SMEM_DYN  (NSTAGE * STAGE_BS)  // 98304

__device__ __forceinline__ void load_tile32(uint32_t dst,
        const __nv_bfloat16* __restrict__ src, int ld, int k0, int tid) {
#pragma unroll
    for (int half = 0; half < 2; half++) {
        const int idx = half * 256 + tid;     // 0..511
        const int row = idx >> 2, c = idx & 3;
        const int sw = c ^ ((row >> 1) & 3);
        cp_async16(dst + (uint32_t)(row * ROWBYTES + sw * 16),
                   src + (size_t)row * ld + k0 + c * 8);
    }
}

__device__ __forceinline__ void load_stage(uint32_t sb,
    const __nv_bfloat16* Ahi, const __nv_bfloat16* Alo, int lda,
    const __nv_bfloat16* Bhi, const __nv_bfloat16* Blo, int ldb,
    int k0, int tid) {
    load_tile32(sb,               Ahi, lda, k0, tid);
    load_tile32(sb + TILE_BS,     Alo, lda, k0, tid);
    load_tile32(sb + 2 * TILE_BS, Bhi, ldb, k0, tid);
    load_tile32(sb + 3 * TILE_BS, Blo, ldb, k0, tid);
}

__device__ __forceinline__ void gemm_mainloop(char* smem,
    const __nv_bfloat16* __restrict__ Ahi, const __nv_bfloat16* __restrict__ Alo, int lda,
    const __nv_bfloat16* __restrict__ Bhi, const __nv_bfloat16* __restrict__ Blo, int ldb,
    int nT, float (&acc)[4][4][4]) {
    const int tid = threadIdx.x;
    const int wid = tid >> 5, lane = tid & 31;
    const int wm = wid & 1, wn = wid >> 1;
    const int mat = lane >> 3, r = lane & 7;
    const int s = (r >> 1) & 3;
    const uint32_t su = smem_to_u32(smem);

    // Per-lane ldmatrix addresses (relative to stage base).
    // LDSM.x4 matrices: mat0=(rows+0..7, chunk j), mat1=(rows+8..15, j),
    // mat2=(rows+0..7, j+1), mat3=(rows+8..15, j+1) with j = kk*2.
    // All later offsets (mi*16, p*16, mat*8 rows) are multiples of 8 rows,
    // so the per-lane swizzle s=(r>>1)&3 is invariant.
    uint32_t aAddr[2], bAddr[2];
#pragma unroll
    for (int kk = 0; kk < 2; kk++) {
        const int ch = (kk * 2 + (mat >> 1)) ^ s;
        aAddr[kk] = (uint32_t)((wm * 64 + (mat & 1) * 8 + r) * ROWBYTES + ch * 16);
        bAddr[kk] = (uint32_t)(2 * TILE_BS +
                               (wn * 32 + (mat & 1) * 8 + r) * ROWBYTES + ch * 16);
    }

    load_stage(su, Ahi, Alo, lda, Bhi, Blo, ldb, 0, tid);
    CP_COMMIT();
    load_stage(su + STAGE_BS, Ahi, Alo, lda, Bhi, Blo, ldb, KT, tid);
    CP_COMMIT();

    uint32_t sb_off = 0;  // (it % 3) * STAGE_BS
    for (int it = 0; it < nT; ++it) {
        if (it + 2 < nT) {
            CP_WAIT(1);
            __syncthreads();
            const uint32_t nb = (sb_off + 2 * STAGE_BS >= 3 * STAGE_BS)
                              ? sb_off - STAGE_BS : sb_off + 2 * STAGE_BS;
            load_stage(su + nb, Ahi, Alo, lda, Bhi, Blo, ldb, (it + 2) * KT, tid);
            CP_COMMIT();
        } else {
            CP_WAIT(0);
            __syncthreads();
        }

        const uint32_t sb = su + sb_off;
#pragma unroll
        for (int kk = 0; kk < 2; kk++) {
            uint32_t bh[4][2], bl[4][2];
#pragma unroll
            for (int p = 0; p < 2; p++) {
                uint32_t r0, r1, r2, r3;
                ldsm_x4(r0, r1, r2, r3, sb + bAddr[kk] + p * 1024);
                bh[2 * p][0] = r0; bh[2 * p + 1][0] = r1;
                bh[2 * p][1] = r2; bh[2 * p + 1][1] = r3;
                ldsm_x4(r0, r1, r2, r3, sb + bAddr[kk] + p * 1024 + TILE_BS);
                bl[2 * p][0] = r0; bl[2 * p + 1][0] = r1;
                bl[2 * p][1] = r2; bl[2 * p + 1][1] = r3;
            }
#pragma unroll
            for (int mi = 0; mi < 4; mi++) {
                uint32_t ah[4], al[4];
                ldsm_x4(ah[0], ah[1], ah[2], ah[3], sb + aAddr[kk] + mi * 1024);
                ldsm_x4(al[0], al[1], al[2], al[3],
                        sb + aAddr[kk] + mi * 1024 + TILE_BS);
#pragma unroll
                for (int ni = 0; ni < 4; ni++) {
                    mma_bf16(acc[mi][ni], ah, bh[ni]);
                    mma_bf16(acc[mi][ni], ah, bl[ni]);
                    mma_bf16(acc[mi][ni], al, bh[ni]);
                }
            }
        }
        __syncthreads();
        sb_off = (sb_off + STAGE_BS >= 3 * STAGE_BS) ? 0 : sb_off + STAGE_BS;
    }
}

// GEMM1: Et32[e][cb*128+h] = L1[e] * sum_n B1T[e,n]*HT[cb][h][n]
__global__ __launch_bounds__(256, 2) void gemm1_kernel() {
    extern __shared__ char smem[];
    float acc[4][4][4];
#pragma unroll
    for (int i = 0; i < 4; i++)
#pragma unroll
        for (int j = 0; j < 4; j++)
#pragma unroll
            for (int k = 0; k < 4; k++) acc[i][j][k] = 0.f;

    const int m0 = blockIdx.x * 128;   // e block
    const int cb = blockIdx.y;         // batch
    gemm_mainloop(smem,
                  g_B1T_hi + (size_t)m0 * Nn, g_B1T_lo + (size_t)m0 * Nn, Nn,
                  g_HT_hi + (size_t)cb * HH * Nn, g_HT_lo + (size_t)cb * HH * Nn, Nn,
                  Nn / KT, acc);

    const int tid = threadIdx.x, lane = tid & 31, wid = tid >> 5;
    const int wm = wid & 1, wn = wid >> 1;
    const int g = lane >> 2, tig = lane & 3;
#pragma unroll
    for (int mi = 0; mi < 4; mi++) {
        const int e = m0 + wm * 64 + mi * 16 + g;
        const float s0 = g_L1[e], s1 = g_L1[e + 8];
        float* r0 = g_Et32 + (size_t)e * CD + cb * 128;
#pragma unroll
        for (int ni = 0; ni < 4; ni++) {
            const int c = wn * 32 + ni * 8 + 2 * tig;
            *(float2*)(r0 + c) = make_float2(acc[mi][ni][0] * s0, acc[mi][ni][1] * s0);
            *(float2*)(r0 + 8 * CD + c) =
                make_float2(acc[mi][ni][2] * s1, acc[mi][ni][3] * s1);
        }
    }
}

// GEMM2 (K-split 2): dHp[sp][cb][n][h] = sum_{e in split sp} B1[n,e]*EtT[cb*128+h][e]
__global__ __launch_bounds__(256, 2) void gemm2_kernel() {
    extern __shared__ char smem[];
    float acc[4][4][4];
#pragma unroll
    for (int i = 0; i < 4; i++)
#pragma unroll
        for (int j = 0; j < 4; j++)
#pragma unroll
            for (int k = 0; k < 4; k++) acc[i][j][k] = 0.f;

    const int m0 = blockIdx.x * 128;   // n block
    const int cb = blockIdx.y;         // batch
    const int sp = blockIdx.z;         // K split
    const size_t ko = (size_t)sp * (Ee / 2);
    gemm_mainloop(smem,
                  g_B1_hi + (size_t)m0 * Ee + ko, g_B1_lo + (size_t)m0 * Ee + ko, Ee,
                  g_EtT_hi + (size_t)cb * 128 * Ee + ko,
                  g_EtT_lo + (size_t)cb * 128 * Ee + ko, Ee,
                  (Ee / 2) / KT, acc);

    const int tid = threadIdx.x, lane = tid & 31, wid = tid >> 5;
    const int wm = wid & 1, wn = wid >> 1;
    const int g = lane >> 2, tig = lane & 3;
    float* outb = g_dH + (size_t)sp * (Bb * Nn * HH);
#pragma unroll
    for (int mi = 0; mi < 4; mi++) {
        const int gn = m0 + wm * 64 + mi * 16 + g;
        float* r0 = outb + ((size_t)cb * Nn + gn) * HH;
        float* r1 = r0 + 8 * HH;
#pragma unroll
        for (int ni = 0; ni < 4; ni++) {
            const int h = wn * 32 + ni * 8 + 2 * tig;
            *(float2*)(r0 + h) = make_float2(acc[mi][ni][0], acc[mi][ni][1]);
            *(float2*)(r1 + h) = make_float2(acc[mi][ni][2], acc[mi][ni][3]);
        }
    }
}

// ---------------------------------------------------------------------------
// Final: out = H + alpha * relu( (dHp0+dHp1) @ W^T )
// ---------------------------------------------------------------------------
__global__ __launch_bounds__(256) void final_kernel(
    const float* __restrict__ H, const float* __restrict__ W,
    const float* __restrict__ alpha_raw, float* __restrict__ out) {
    __shared__ float As[32][132];
    __shared__ float Ws[32][132];
    const int tid = threadIdx.x;
    const int tx = tid & 15, ty = tid >> 4;
    const int m0 = blockIdx.x * 128;
    const int r = tid >> 3, c4 = (tid & 7) * 4;
    const size_t DHP = (size_t)Bb * Nn * HH;

    float acc[8][8];
#pragma unroll
    for (int i = 0; i < 8; i++)
#pragma unroll
        for (int j = 0; j < 8; j++) acc[i][j] = 0.f;

    for (int h0 = 0; h0 < HH; h0 += 32) {
        __syncthreads();
#pragma unroll
        for (int p = 0; p < 4; p++) {
            const int row = r + p * 32;
            const size_t ai = (size_t)(m0 + row) * HH + h0 + c4;
            float4 a0 = *(const float4*)(g_dH + ai);
            float4 a1 = *(const float4*)(g_dH + DHP + ai);
            As[c4 + 0][row] = a0.x + a1.x; As[c4 + 1][row] = a0.y + a1.y;
            As[c4 + 2][row] = a0.z + a1.z; As[c4 + 3][row] = a0.w + a1.w;
            float4 wv = *(const float4*)(W + (size_t)row * HH + h0 + c4);
            Ws[c4 + 0][row] = wv.x; Ws[c4 + 1][row] = wv.y;
            Ws[c4 + 2][row] = wv.z; Ws[c4 + 3][row] = wv.w;
        }
        __syncthreads();
#pragma unroll
        for (int kk = 0; kk < 32; kk++) {
            float a[8], w[8];
            *(float4*)(a)     = *(const float4*)&As[kk][ty * 8];
            *(float4*)(a + 4) = *(const float4*)&As[kk][ty * 8 + 4];
            *(float4*)(w)     = *(const float4*)&Ws[kk][tx * 8];
            *(float4*)(w + 4) = *(const float4*)&Ws[kk][tx * 8 + 4];
#pragma unroll
            for (int i = 0; i < 8; i++)
#pragma unroll
                for (int j = 0; j < 8; j++)
                    acc[i][j] = fmaf(a[i], w[j], acc[i][j]);
        }
    }

    const float alpha = 0.05f / (1.0f + expf(-alpha_raw[0]));
#pragma unroll
    for (int i = 0; i < 8; i++) {
        const size_t m = (size_t)m0 + ty * 8 + i;
        const float* Hr = H + m * HH + tx * 8;
        float* Or = out + m * HH + tx * 8;
#pragma unroll
        for (int j = 0; j < 8; j++)
            Or[j] = Hr[j] + alpha * fmaxf(acc[i][j], 0.f);
    }
}

// ---------------------------------------------------------------------------
extern "C" void kernel_launch(void* const* d_in, const int* in_sizes, int n_in,
                              void* d_out, int out_size) {
    const float* H  = (const float*)d_in[0];
    const float* B1 = (const float*)d_in[1];
    const float* B2 = (const float*)d_in[2];
    const float* W  = (const float*)d_in[3];
    const float* ar = (const float*)d_in[4];
    float* out = (float*)d_out;

    cudaFuncSetAttribute(gemm1_kernel, cudaFuncAttributeMaxDynamicSharedMemorySize, SMEM_DYN);
    cudaFuncSetAttribute(gemm2_kernel, cudaFuncAttributeMaxDynamicSharedMemorySize, SMEM_DYN);

    // B1 [N,E] -> B1T hi/lo [E,N] + B1 hi/lo [N,E] + L1 partials (one read)
    tsplit_b1_kernel<<<dim3(Ee / 32, Nn / 32, 1), dim3(32, 8)>>>(B1);
    // H [b][n][h] -> HT hi/lo [b][h][n]
    tsplit_h_kernel<<<dim3(HH / 32, Nn / 32, Bb), dim3(32, 8)>>>(H);
    // L1[e] = sum partials + rowsum(B2^2)
    l1_finalize_kernel<<<Ee / 8, 256>>>(B2);

    // GEMM1 -> Et32 fp32 [E][CD]
    gemm1_kernel<<<dim3(Ee / 128, Bb), 256, SMEM_DYN>>>();
    // Et32 [E][CD] -> EtT hi/lo [CD][E]
    tsplit_et_kernel<<<dim3(CD / 32, Ee / 32, 1), dim3(32, 8)>>>();
    // GEMM2 (K-split 2) -> dH partials
    gemm2_kernel<<<dim3(Nn / 128, Bb, 2), 256, SMEM_DYN>>>();
    final_kernel<<<(Bb * Nn) / 128, 256>>>(H, W, ar, out);
}

// round 12
// speedup vs baseline: 2.1748x; 1.0026x over previous
#include <cuda_runtime.h>
#include <cuda_bf16.h>
#include <cstdint>
#include <math.h>

// Problem dims
#define Bb   8
#define Nn   2048
#define Ee   8192
#define Tt   4096
#define HH   128
#define CD   1024   // B*HH

// ---------------------------------------------------------------------------
// Scratch (static device globals). NEVER pass these as kernel arguments from
// host code (host shadow symbol + GB300 ATS silently writes host memory —
// the R8/R9 bug). All bindings happen inside device code.
// ---------------------------------------------------------------------------
__device__ __nv_bfloat16 g_B1T_hi[(size_t)Ee * Nn];      // B1^T  [E,N]
__device__ __nv_bfloat16 g_B1T_lo[(size_t)Ee * Nn];
__device__ __nv_bfloat16 g_B1_hi [(size_t)Nn * Ee];      // B1    [N,E]
__device__ __nv_bfloat16 g_B1_lo [(size_t)Nn * Ee];
__device__ __nv_bfloat16 g_HT_hi [(size_t)Bb * HH * Nn]; // H^T [b][h][n]
__device__ __nv_bfloat16 g_HT_lo [(size_t)Bb * HH * Nn];
__device__ float         g_Et32  [(size_t)Ee * CD];      // Etopo [e][b*128+h] fp32
__device__ __nv_bfloat16 g_EtT_hi[(size_t)CD * Ee];      // Etopo^T [b*128+h][e]
__device__ __nv_bfloat16 g_EtT_lo[(size_t)CD * Ee];
__device__ float g_dH[(size_t)2 * Bb * Nn * HH];         // 2 K-split partials
__device__ float g_L1[Ee];
__device__ float g_L1part[64][Ee];

// ---------------------------------------------------------------------------
// Base-ISA helpers (sm_80 features only — plain compute_103 safe)
// ---------------------------------------------------------------------------
__device__ __forceinline__ uint32_t smem_to_u32(const void* p) {
    uint32_t a;
    asm("{ .reg .u64 t; cvta.to.shared.u64 t, %1; cvt.u32.u64 %0, t; }"
        : "=r"(a) : "l"(p));
    return a;
}
#define CP_COMMIT() asm volatile("cp.async.commit_group;" ::: "memory")
#define CP_WAIT(n)  asm volatile("cp.async.wait_group %0;" :: "n"(n) : "memory")

__device__ __forceinline__ void cp_async16(uint32_t dst, const void* src) {
    asm volatile("cp.async.cg.shared.global [%0], [%1], 16;" :: "r"(dst), "l"(src));
}
__device__ __forceinline__ void ldsm_x4(uint32_t& r0, uint32_t& r1,
                                        uint32_t& r2, uint32_t& r3, uint32_t a) {
    asm volatile("ldmatrix.sync.aligned.m8n8.x4.shared.b16 {%0,%1,%2,%3}, [%4];"
                 : "=r"(r0), "=r"(r1), "=r"(r2), "=r"(r3) : "r"(a));
}
__device__ __forceinline__ void mma_bf16(float d[4], const uint32_t a[4],
                                         const uint32_t b[2]) {
    asm volatile(
        "mma.sync.aligned.m16n8k16.row.col.f32.bf16.bf16.f32 "
        "{%0,%1,%2,%3}, {%4,%5,%6,%7}, {%8,%9}, {%0,%1,%2,%3};"
        : "+f"(d[0]), "+f"(d[1]), "+f"(d[2]), "+f"(d[3])
        : "r"(a[0]), "r"(a[1]), "r"(a[2]), "r"(a[3]), "r"(b[0]), "r"(b[1]));
}
__device__ __forceinline__ void bf16_split(float a, __nv_bfloat16& h, __nv_bfloat16& l) {
    h = __float2bfloat16(a);
    l = __float2bfloat16(a - __bfloat162float(h));
}

// ---------------------------------------------------------------------------
// Prep kernels. tsplit = 32x32 transpose + bf16 hi/lo split.
// ---------------------------------------------------------------------------
__device__ __forceinline__ void tsplit_body(
    const float* __restrict__ in, int ld_in,
    __nv_bfloat16* __restrict__ hi, __nv_bfloat16* __restrict__ lo,
    int ld_out) {
    __shared__ float t[32][33];
    const int r0 = blockIdx.y * 32, c0 = blockIdx.x * 32;
    const int x = threadIdx.x, y = threadIdx.y;
#pragma unroll
    for (int i = 0; i < 32; i += 8)
        t[y + i][x] = in[(size_t)(r0 + y + i) * ld_in + c0 + x];
    __syncthreads();
#pragma unroll
    for (int i = 0; i < 32; i += 8) {
        float v = t[x][y + i];
        __nv_bfloat16 h, l;
        bf16_split(v, h, l);
        size_t o = (size_t)(c0 + y + i) * ld_out + r0 + x;
        hi[o] = h; lo[o] = l;
    }
}

// B1 [N,E]: emits B1T hi/lo [E,N] (transposed), B1 hi/lo [N,E] (straight),
// and per-32-row-block L1 partial sums. One read of B1.
__global__ void tsplit_b1_kernel(const float* __restrict__ B1) {
    __shared__ float t[32][33];
    __shared__ float ps[8][32];
    const int r0 = blockIdx.y * 32, c0 = blockIdx.x * 32;
    const int x = threadIdx.x, y = threadIdx.y;
    float s = 0.f;
#pragma unroll
    for (int i = 0; i < 32; i += 8) {
        float v = B1[(size_t)(r0 + y + i) * Ee + c0 + x];
        t[y + i][x] = v;
        s += v * v;
        __nv_bfloat16 h, l;
        bf16_split(v, h, l);
        const size_t o = (size_t)(r0 + y + i) * Ee + c0 + x;
        g_B1_hi[o] = h; g_B1_lo[o] = l;
    }
    ps[y][x] = s;
    __syncthreads();
    if (y == 0) {
        float tot = 0.f;
#pragma unroll
        for (int k = 0; k < 8; k++) tot += ps[k][x];
        g_L1part[blockIdx.y][c0 + x] = tot;
    }
#pragma unroll
    for (int i = 0; i < 32; i += 8) {
        float v = t[x][y + i];
        __nv_bfloat16 h, l;
        bf16_split(v, h, l);
        size_t o = (size_t)(c0 + y + i) * Nn + r0 + x;
        g_B1T_hi[o] = h; g_B1T_lo[o] = l;
    }
}

// H [b][n][h] -> g_HT hi/lo [b][h][n]
__global__ void tsplit_h_kernel(const float* __restrict__ H) {
    const size_t ib = (size_t)blockIdx.z * (Nn * HH);
    const size_t ob = (size_t)blockIdx.z * (HH * Nn);
    tsplit_body(H + ib, HH, g_HT_hi + ob, g_HT_lo + ob, Nn);
}
// Et32 [E][CD] -> g_EtT hi/lo [CD][E]
__global__ void tsplit_et_kernel() {
    tsplit_body(g_Et32, CD, g_EtT_hi, g_EtT_lo, Ee);
}

__global__ void l1_finalize_kernel(const float* __restrict__ B2) {
    const int warp = threadIdx.x >> 5, lane = threadIdx.x & 31;
    const int e = blockIdx.x * 8 + warp;
    float s = 0.f;
#pragma unroll
    for (int p = lane; p < 64; p += 32) s += g_L1part[p][e];
    const float* r2 = B2 + (size_t)e * Tt;
    for (int i = lane * 4; i < Tt; i += 128) {
        float4 v = *(const float4*)(r2 + i);
        s += v.x * v.x + v.y * v.y + v.z * v.z + v.w * v.w;
    }
#pragma unroll
    for (int o = 16; o; o >>= 1) s += __shfl_xor_sync(0xffffffffu, s, o);
    if (lane == 0) g_L1[e] = s;
}

// ---------------------------------------------------------------------------
// mma.sync GEMM core with ldmatrix fragments.
// C[128,128] += A[128,K]*B[128,K]^T, hi/lo bf16, 3-MMA fp32 emulation.
// K-tile 32, rows of 64B, XOR swizzle chunk' = chunk ^ ((row>>1)&3).
// 3-stage cp.async pipeline, 96KB smem -> 2 CTAs/SM. 8 warps = 2(m) x 4(n).
// R12: pass-major MMA order (same-acc reuse distance 1 -> 4) + A-fragment
// double buffering across mi (hides LDSM->HMMA latency).
// ---------------------------------------------------------------------------
#define KT        32
#define ROWBYTES  64
#define TILE_BS   8192                 // 128 rows * 64B
#define STAGE_BS  (4 * TILE_BS)        // Ahi Alo Bhi Blo = 32KB
#define NSTAGE    3
#define SMEM_DYN  (NSTAGE * STAGE_BS)  // 98304

__device__ __forceinline__ void load_tile32(uint32_t dst,
        const __nv_bfloat16* __restrict__ src, int ld, int k0, int tid) {
#pragma unroll
    for (int half = 0; half < 2; half++) {
        const int idx = half * 256 + tid;     // 0..511
        const int row = idx >> 2, c = idx & 3;
        const int sw = c ^ ((row >> 1) & 3);
        cp_async16(dst + (uint32_t)(row * ROWBYTES + sw * 16),
                   src + (size_t)row * ld + k0 + c * 8);
    }
}

__device__ __forceinline__ void load_stage(uint32_t sb,
    const __nv_bfloat16* Ahi, const __nv_bfloat16* Alo, int lda,
    const __nv_bfloat16* Bhi, const __nv_bfloat16* Blo, int ldb,
    int k0, int tid) {
    load_tile32(sb,               Ahi, lda, k0, tid);
    load_tile32(sb + TILE_BS,     Alo, lda, k0, tid);
    load_tile32(sb + 2 * TILE_BS, Bhi, ldb, k0, tid);
    load_tile32(sb + 3 * TILE_BS, Blo, ldb, k0, tid);
}

__device__ __forceinline__ void gemm_mainloop(char* smem,
    const __nv_bfloat16* __restrict__ Ahi, const __nv_bfloat16* __restrict__ Alo, int lda,
    const __nv_bfloat16* __restrict__ Bhi, const __nv_bfloat16* __restrict__ Blo, int ldb,
    int nT, float (&acc)[4][4][4]) {
    const int tid = threadIdx.x;
    const int wid = tid >> 5, lane = tid & 31;
    const int wm = wid & 1, wn = wid >> 1;
    const int mat = lane >> 3, r = lane & 7;
    const int s = (r >> 1) & 3;
    const uint32_t su = smem_to_u32(smem);

    // Per-lane ldmatrix addresses (relative to stage base); swizzle constant
    // across mi/p/mat offsets (all multiples of 8 rows).
    uint32_t aAddr[2], bAddr[2];
#pragma unroll
    for (int kk = 0; kk < 2; kk++) {
        const int ch = (kk * 2 + (mat >> 1)) ^ s;
        aAddr[kk] = (uint32_t)((wm * 64 + (mat & 1) * 8 + r) * ROWBYTES + ch * 16);
        bAddr[kk] = (uint32_t)(2 * TILE_BS +
                               (wn * 32 + (mat & 1) * 8 + r) * ROWBYTES + ch * 16);
    }

    load_stage(su, Ahi, Alo, lda, Bhi, Blo, ldb, 0, tid);
    CP_COMMIT();
    load_stage(su + STAGE_BS, Ahi, Alo, lda, Bhi, Blo, ldb, KT, tid);
    CP_COMMIT();

    uint32_t sb_off = 0;  // (it % 3) * STAGE_BS
    for (int it = 0; it < nT; ++it) {
        if (it + 2 < nT) {
            CP_WAIT(1);
            __syncthreads();
            const uint32_t nb = (sb_off + 2 * STAGE_BS >= 3 * STAGE_BS)
                              ? sb_off - STAGE_BS : sb_off + 2 * STAGE_BS;
            load_stage(su + nb, Ahi, Alo, lda, Bhi, Blo, ldb, (it + 2) * KT, tid);
            CP_COMMIT();
        } else {
            CP_WAIT(0);
            __syncthreads();
        }

        const uint32_t sb = su + sb_off;
#pragma unroll
        for (int kk = 0; kk < 2; kk++) {
            uint32_t bh[4][2], bl[4][2];
#pragma unroll
            for (int p = 0; p < 2; p++) {
                uint32_t r0, r1, r2, r3;
                ldsm_x4(r0, r1, r2, r3, sb + bAddr[kk] + p * 1024);
                bh[2 * p][0] = r0; bh[2 * p + 1][0] = r1;
                bh[2 * p][1] = r2; bh[2 * p + 1][1] = r3;
                ldsm_x4(r0, r1, r2, r3, sb + bAddr[kk] + p * 1024 + TILE_BS);
                bl[2 * p][0] = r0; bl[2 * p + 1][0] = r1;
                bl[2 * p][1] = r2; bl[2 * p + 1][1] = r3;
            }
            // A-fragment double buffer across mi; pass-major MMA issue so the
            // 3 emulation MMAs of one accumulator are 4 apart, not adjacent.
            uint32_t ah[2][4], al[2][4];
            ldsm_x4(ah[0][0], ah[0][1], ah[0][2], ah[0][3], sb + aAddr[kk]);
            ldsm_x4(al[0][0], al[0][1], al[0][2], al[0][3],
                    sb + aAddr[kk] + TILE_BS);
#pragma unroll
            for (int mi = 0; mi < 4; mi++) {
                const int cur = mi & 1, nxt = cur ^ 1;
                if (mi < 3) {
                    ldsm_x4(ah[nxt][0], ah[nxt][1], ah[nxt][2], ah[nxt][3],
                            sb + aAddr[kk] + (mi + 1) * 1024);
                    ldsm_x4(al[nxt][0], al[nxt][1], al[nxt][2], al[nxt][3],
                            sb + aAddr[kk] + (mi + 1) * 1024 + TILE_BS);
                }
#pragma unroll
                for (int ni = 0; ni < 4; ni++) mma_bf16(acc[mi][ni], ah[cur], bh[ni]);
#pragma unroll
                for (int ni = 0; ni < 4; ni++) mma_bf16(acc[mi][ni], ah[cur], bl[ni]);
#pragma unroll
                for (int ni = 0; ni < 4; ni++) mma_bf16(acc[mi][ni], al[cur], bh[ni]);
            }
        }
        __syncthreads();
        sb_off = (sb_off + STAGE_BS >= 3 * STAGE_BS) ? 0 : sb_off + STAGE_BS;
    }
}

// GEMM1: Et32[e][cb*128+h] = L1[e] * sum_n B1T[e,n]*HT[cb][h][n]
__global__ __launch_bounds__(256, 2) void gemm1_kernel() {
    extern __shared__ char smem[];
    float acc[4][4][4];
#pragma unroll
    for (int i = 0; i < 4; i++)
#pragma unroll
        for (int j = 0; j < 4; j++)
#pragma unroll
            for (int k = 0; k < 4; k++) acc[i][j][k] = 0.f;

    const int m0 = blockIdx.x * 128;   // e block
    const int cb = blockIdx.y;         // batch
    gemm_mainloop(smem,
                  g_B1T_hi + (size_t)m0 * Nn, g_B1T_lo + (size_t)m0 * Nn, Nn,
                  g_HT_hi + (size_t)cb * HH * Nn, g_HT_lo + (size_t)cb * HH * Nn, Nn,
                  Nn / KT, acc);

    const int tid = threadIdx.x, lane = tid & 31, wid = tid >> 5;
    const int wm = wid & 1, wn = wid >> 1;
    const int g = lane >> 2, tig = lane & 3;
#pragma unroll
    for (int mi = 0; mi < 4; mi++) {
        const int e = m0 + wm * 64 + mi * 16 + g;
        const float s0 = g_L1[e], s1 = g_L1[e + 8];
        float* r0 = g_Et32 + (size_t)e * CD + cb * 128;
#pragma unroll
        for (int ni = 0; ni < 4; ni++) {
            const int c = wn * 32 + ni * 8 + 2 * tig;
            *(float2*)(r0 + c) = make_float2(acc[mi][ni][0] * s0, acc[mi][ni][1] * s0);
            *(float2*)(r0 + 8 * CD + c) =
                make_float2(acc[mi][ni][2] * s1, acc[mi][ni][3] * s1);
        }
    }
}

// GEMM2 (K-split 2): dHp[sp][cb][n][h] = sum_{e in split sp} B1[n,e]*EtT[cb*128+h][e]
__global__ __launch_bounds__(256, 2) void gemm2_kernel() {
    extern __shared__ char smem[];
    float acc[4][4][4];
#pragma unroll
    for (int i = 0; i < 4; i++)
#pragma unroll
        for (int j = 0; j < 4; j++)
#pragma unroll
            for (int k = 0; k < 4; k++) acc[i][j][k] = 0.f;

    const int m0 = blockIdx.x * 128;   // n block
    const int cb = blockIdx.y;         // batch
    const int sp = blockIdx.z;         // K split
    const size_t ko = (size_t)sp * (Ee / 2);
    gemm_mainloop(smem,
                  g_B1_hi + (size_t)m0 * Ee + ko, g_B1_lo + (size_t)m0 * Ee + ko, Ee,
                  g_EtT_hi + (size_t)cb * 128 * Ee + ko,
                  g_EtT_lo + (size_t)cb * 128 * Ee + ko, Ee,
                  (Ee / 2) / KT, acc);

    const int tid = threadIdx.x, lane = tid & 31, wid = tid >> 5;
    const int wm = wid & 1, wn = wid >> 1;
    const int g = lane >> 2, tig = lane & 3;
    float* outb = g_dH + (size_t)sp * (Bb * Nn * HH);
#pragma unroll
    for (int mi = 0; mi < 4; mi++) {
        const int gn = m0 + wm * 64 + mi * 16 + g;
        float* r0 = outb + ((size_t)cb * Nn + gn) * HH;
        float* r1 = r0 + 8 * HH;
#pragma unroll
        for (int ni = 0; ni < 4; ni++) {
            const int h = wn * 32 + ni * 8 + 2 * tig;
            *(float2*)(r0 + h) = make_float2(acc[mi][ni][0], acc[mi][ni][1]);
            *(float2*)(r1 + h) = make_float2(acc[mi][ni][2], acc[mi][ni][3]);
        }
    }
}

// ---------------------------------------------------------------------------
// Final: out = H + alpha * relu( (dHp0+dHp1) @ W^T )
// ---------------------------------------------------------------------------
__global__ __launch_bounds__(256) void final_kernel(
    const float* __restrict__ H, const float* __restrict__ W,
    const float* __restrict__ alpha_raw, float* __restrict__ out) {
    __shared__ float As[32][132];
    __shared__ float Ws[32][132];
    const int tid = threadIdx.x;
    const int tx = tid & 15, ty = tid >> 4;
    const int m0 = blockIdx.x * 128;
    const int r = tid >> 3, c4 = (tid & 7) * 4;
    const size_t DHP = (size_t)Bb * Nn * HH;

    float acc[8][8];
#pragma unroll
    for (int i = 0; i < 8; i++)
#pragma unroll
        for (int j = 0; j < 8; j++) acc[i][j] = 0.f;

    for (int h0 = 0; h0 < HH; h0 += 32) {
        __syncthreads();
#pragma unroll
        for (int p = 0; p < 4; p++) {
            const int row = r + p * 32;
            const size_t ai = (size_t)(m0 + row) * HH + h0 + c4;
            float4 a0 = *(const float4*)(g_dH + ai);
            float4 a1 = *(const float4*)(g_dH + DHP + ai);
            As[c4 + 0][row] = a0.x + a1.x; As[c4 + 1][row] = a0.y + a1.y;
            As[c4 + 2][row] = a0.z + a1.z; As[c4 + 3][row] = a0.w + a1.w;
            float4 wv = *(const float4*)(W + (size_t)row * HH + h0 + c4);
            Ws[c4 + 0][row] = wv.x; Ws[c4 + 1][row] = wv.y;
            Ws[c4 + 2][row] = wv.z; Ws[c4 + 3][row] = wv.w;
        }
        __syncthreads();
#pragma unroll
        for (int kk = 0; kk < 32; kk++) {
            float a[8], w[8];
            *(float4*)(a)     = *(const float4*)&As[kk][ty * 8];
            *(float4*)(a + 4) = *(const float4*)&As[kk][ty * 8 + 4];
            *(float4*)(w)     = *(const float4*)&Ws[kk][tx * 8];
            *(float4*)(w + 4) = *(const float4*)&Ws[kk][tx * 8 + 4];
#pragma unroll
            for (int i = 0; i < 8; i++)
#pragma unroll
                for (int j = 0; j < 8; j++)
                    acc[i][j] = fmaf(a[i], w[j], acc[i][j]);
        }
    }

    const float alpha = 0.05f / (1.0f + expf(-alpha_raw[0]));
#pragma unroll
    for (int i = 0; i < 8; i++) {
        const size_t m = (size_t)m0 + ty * 8 + i;
        const float* Hr = H + m * HH + tx * 8;
        float* Or = out + m * HH + tx * 8;
#pragma unroll
        for (int j = 0; j < 8; j++)
            Or[j] = Hr[j] + alpha * fmaxf(acc[i][j], 0.f);
    }
}

// ---------------------------------------------------------------------------
extern "C" void kernel_launch(void* const* d_in, const int* in_sizes, int n_in,
                              void* d_out, int out_size) {
    const float* H  = (const float*)d_in[0];
    const float* B1 = (const float*)d_in[1];
    const float* B2 = (const float*)d_in[2];
    const float* W  = (const float*)d_in[3];
    const float* ar = (const float*)d_in[4];
    float* out = (float*)d_out;

    cudaFuncSetAttribute(gemm1_kernel, cudaFuncAttributeMaxDynamicSharedMemorySize, SMEM_DYN);
    cudaFuncSetAttribute(gemm2_kernel, cudaFuncAttributeMaxDynamicSharedMemorySize, SMEM_DYN);

    // B1 [N,E] -> B1T hi/lo [E,N] + B1 hi/lo [N,E] + L1 partials (one read)
    tsplit_b1_kernel<<<dim3(Ee / 32, Nn / 32, 1), dim3(32, 8)>>>(B1);
    // H [b][n][h] -> HT hi/lo [b][h][n]
    tsplit_h_kernel<<<dim3(HH / 32, Nn / 32, Bb), dim3(32, 8)>>>(H);
    // L1[e] = sum partials + rowsum(B2^2)
    l1_finalize_kernel<<<Ee / 8, 256>>>(B2);

    // GEMM1 -> Et32 fp32 [E][CD]
    gemm1_kernel<<<dim3(Ee / 128, Bb), 256, SMEM_DYN>>>();
    // Et32 [E][CD] -> EtT hi/lo [CD][E]
    tsplit_et_kernel<<<dim3(CD / 32, Ee / 32, 1), dim3(32, 8)>>>();
    // GEMM2 (K-split 2) -> dH partials
    gemm2_kernel<<<dim3(Nn / 128, Bb, 2), 256, SMEM_DYN>>>();
    final_kernel<<<(Bb * Nn) / 128, 256>>>(H, W, ar, out);
}